// round 7
// baseline (speedup 1.0000x reference)
#include <cuda_runtime.h>
#include <cuda_bf16.h>
#include <math.h>

// Problem dims
#define Bc 32
#define Sc 512
#define Ic 256
#define Hc 1024
#define Oc 256
#define HID_OFF (Bc*Sc*Oc)   // floats: out (B,S,O) first, then hidden (B,2,H)
#define THREADS 512
#define WSTRIDE 1028         // padded weight row (floats): 4-float pad -> conflict-free lane-distributed float4 loads

// ---------------- scratch (__device__ globals: allocation-free) ----------------
// layout of all [S][H][B] tensors: idx = (t*Hc + j)*Bc + b
__device__ float g_xz[Sc*Hc*Bc];
__device__ float g_xr[Sc*Hc*Bc];
__device__ float g_xg[Sc*Hc*Bc];
__device__ float g_y [Sc*Hc*Bc];
__device__ float g_h [Hc*Bc];    // [j][b]
__device__ float g_rh[Hc*Bc];    // [j][b]

// ---------------- two-level grid barrier state ----------------
__device__ unsigned g_sub[16];
__device__ unsigned g_master;
__device__ unsigned g_gen;

__device__ __forceinline__ unsigned ld_acq(const unsigned* p) {
    unsigned v;
    asm volatile("ld.acquire.gpu.u32 %0, [%1];" : "=r"(v) : "l"(p) : "memory");
    return v;
}
__device__ __forceinline__ void st_rel(unsigned* p, unsigned v) {
    asm volatile("st.release.gpu.u32 [%0], %1;" :: "l"(p), "r"(v) : "memory");
}
__device__ __forceinline__ void st_rlx(unsigned* p, unsigned v) {
    asm volatile("st.relaxed.gpu.u32 [%0], %1;" :: "l"(p), "r"(v) : "memory");
}
__device__ __forceinline__ unsigned atom_add_acqrel(unsigned* p, unsigned v) {
    unsigned o;
    asm volatile("atom.add.acq_rel.gpu.u32 %0, [%1], %2;" : "=r"(o) : "l"(p), "r"(v) : "memory");
    return o;
}

// All blocks must call with the same monotonically increasing target.
__device__ __forceinline__ void grid_bar(int bid, int NB, unsigned target) {
    __syncthreads();
    if (threadIdx.x == 0) {
        int s = bid & 15;
        unsigned quota = (unsigned)((NB - 1 - s) / 16 + 1);
        unsigned o = atom_add_acqrel(&g_sub[s], 1u);
        if (o == quota - 1u) {
            st_rlx(&g_sub[s], 0u);
            unsigned nsub = (unsigned)((NB < 16) ? NB : 16);
            unsigned m = atom_add_acqrel(&g_master, 1u);
            if (m == nsub - 1u) {
                st_rlx(&g_master, 0u);
                st_rel(&g_gen, target);
            }
        }
        while ((int)(ld_acq(&g_gen) - target) < 0) { }
    }
    __syncthreads();
}

__device__ __forceinline__ float sigm(float x) {
    return 1.0f / (1.0f + __expf(-x));
}
__device__ __forceinline__ float fast_tanh(float x) {
    float ax = fabsf(x);
    float e = __expf(2.0f * ax);
    float t = 1.0f - 2.0f / (e + 1.0f);   // e=inf -> 1
    return copysignf(t, x);
}

// ---------------- mbarrier + bulk-copy helpers ----------------
__device__ __forceinline__ unsigned s2u(const void* p) {
    unsigned a;
    asm("{ .reg .u64 t; cvta.to.shared.u64 t, %1; cvt.u32.u64 %0, t; }" : "=r"(a) : "l"(p));
    return a;
}
__device__ __forceinline__ void mb_init(unsigned a) {
    asm volatile("mbarrier.init.shared.b64 [%0], 1;" :: "r"(a) : "memory");
}
__device__ __forceinline__ void mb_expect(unsigned a, unsigned bytes) {
    asm volatile("mbarrier.arrive.expect_tx.shared.b64 _, [%0], %1;" :: "r"(a), "r"(bytes) : "memory");
}
__device__ __forceinline__ void g2s(unsigned dst, const float* src, unsigned bytes, unsigned mb) {
    asm volatile("cp.async.bulk.shared::cta.global.mbarrier::complete_tx::bytes [%0], [%1], %2, [%3];"
                 :: "r"(dst), "l"(src), "r"(bytes), "r"(mb) : "memory");
}
__device__ __forceinline__ void mb_wait(unsigned a, unsigned parity) {
    unsigned done;
    asm volatile("{\n\t.reg .pred p;\n\t"
                 "mbarrier.try_wait.parity.acquire.cta.shared::cta.b64 p, [%1], %2;\n\t"
                 "selp.b32 %0, 1, 0, p;\n\t}"
                 : "=r"(done) : "r"(a), "r"(parity) : "memory");
    while (!done) {
        asm volatile("{\n\t.reg .pred p;\n\t"
                     "mbarrier.try_wait.parity.acquire.cta.shared::cta.b64 p, [%1], %2, 0x989680;\n\t"
                     "selp.b32 %0, 1, 0, p;\n\t}"
                     : "=r"(done) : "r"(a), "r"(parity) : "memory");
    }
}

// packed f32x2 helpers
__device__ __forceinline__ unsigned long long dup2(float w) {
    unsigned long long d;
    unsigned r = __float_as_uint(w);
    asm("mov.b64 %0, {%1, %1};" : "=l"(d) : "r"(r));
    return d;
}
#define FMA2(acc, h, w) asm("fma.rn.f32x2 %0, %1, %2, %0;" : "+l"(acc) : "l"(h), "l"(w))
#define LDSV2B64(h01, h23, addr) \
    asm("ld.shared.v2.b64 {%0, %1}, [%2];" : "=l"(h01), "=l"(h23) : "r"(addr))
#define UNPK2(r0, r1, a) asm("mov.b64 {%0, %1}, %2;" : "=r"(r0), "=r"(r1) : "l"(a))

// ---------------- input projection GEMM ----------------
__global__ void __launch_bounds__(256) proj_kernel(
    const float* __restrict__ X,
    const float* __restrict__ W0, const float* __restrict__ bv0,
    const float* __restrict__ W1, const float* __restrict__ bv1,
    const float* __restrict__ W2, const float* __restrict__ bv2,
    int K, int alayout)
{
    __shared__ float A_sm[32 * 33];
    __shared__ float W_sm[32 * 132];

    const int t = blockIdx.x;
    const int j0 = blockIdx.y * 128;
    const int gate = blockIdx.z;
    const float* W    = (gate == 0) ? W0  : (gate == 1) ? W1  : W2;
    const float* bias = (gate == 0) ? bv0 : (gate == 1) ? bv1 : bv2;
    float* out        = (gate == 0) ? g_xz : (gate == 1) ? g_xr : g_xg;

    const int tid = threadIdx.x;
    const int jg = tid & 31;
    const int bg = tid >> 5;

    float acc[4][4];
#pragma unroll
    for (int jq = 0; jq < 4; jq++) {
        float bvv = bias[j0 + jg * 4 + jq];
        acc[0][jq] = bvv; acc[1][jq] = bvv; acc[2][jq] = bvv; acc[3][jq] = bvv;
    }

    for (int k0 = 0; k0 < K; k0 += 32) {
        if (alayout == 0) {
            int kk = tid & 31, br = tid >> 5;
#pragma unroll
            for (int p = 0; p < 4; p++) {
                int b = br + p * 8;
                A_sm[kk * 33 + b] = X[((size_t)b * Sc + t) * K + k0 + kk];
            }
        } else {
            int b = tid & 31, kr = tid >> 5;
#pragma unroll
            for (int p = 0; p < 4; p++) {
                int kk = kr + p * 8;
                A_sm[kk * 33 + b] = g_y[((size_t)t * K + k0 + kk) * Bc + b];
            }
        }
        {
            int kk = tid & 31, jr = tid >> 5;
#pragma unroll
            for (int p = 0; p < 16; p++) {
                int jj = jr + p * 8;
                W_sm[kk * 132 + jj] = W[(size_t)(j0 + jj) * K + k0 + kk];
            }
        }
        __syncthreads();

#pragma unroll 8
        for (int kk = 0; kk < 32; kk++) {
            float4 wv = *(const float4*)&W_sm[kk * 132 + jg * 4];
            float a0 = A_sm[kk * 33 + bg * 4 + 0];
            float a1 = A_sm[kk * 33 + bg * 4 + 1];
            float a2 = A_sm[kk * 33 + bg * 4 + 2];
            float a3 = A_sm[kk * 33 + bg * 4 + 3];
            acc[0][0] += a0 * wv.x; acc[0][1] += a0 * wv.y; acc[0][2] += a0 * wv.z; acc[0][3] += a0 * wv.w;
            acc[1][0] += a1 * wv.x; acc[1][1] += a1 * wv.y; acc[1][2] += a1 * wv.z; acc[1][3] += a1 * wv.w;
            acc[2][0] += a2 * wv.x; acc[2][1] += a2 * wv.y; acc[2][2] += a2 * wv.z; acc[2][3] += a2 * wv.w;
            acc[3][0] += a3 * wv.x; acc[3][1] += a3 * wv.y; acc[3][2] += a3 * wv.z; acc[3][3] += a3 * wv.w;
        }
        __syncthreads();
    }

#pragma unroll
    for (int jq = 0; jq < 4; jq++) {
        int j = j0 + jg * 4 + jq;
        float4 v = make_float4(acc[0][jq], acc[1][jq], acc[2][jq], acc[3][jq]);
        *(float4*)&out[((size_t)t * Hc + j) * Bc + bg * 4] = v;
    }
}

// ---------------- output projection ----------------
__global__ void __launch_bounds__(256) outproj_kernel(
    const float* __restrict__ Wout, const float* __restrict__ bout,
    float* __restrict__ dout)
{
    __shared__ float A_sm[32 * 33];
    __shared__ float W_sm[32 * 132];

    const int t = blockIdx.x;
    const int j0 = blockIdx.y * 128;
    const int tid = threadIdx.x;
    const int jg = tid & 31;
    const int bg = tid >> 5;
    const int K = Hc;

    float acc[4][4];
#pragma unroll
    for (int jq = 0; jq < 4; jq++) {
        float bvv = bout[j0 + jg * 4 + jq];
        acc[0][jq] = bvv; acc[1][jq] = bvv; acc[2][jq] = bvv; acc[3][jq] = bvv;
    }

    for (int k0 = 0; k0 < K; k0 += 32) {
        {
            int b = tid & 31, kr = tid >> 5;
#pragma unroll
            for (int p = 0; p < 4; p++) {
                int kk = kr + p * 8;
                A_sm[kk * 33 + b] = g_y[((size_t)t * K + k0 + kk) * Bc + b];
            }
        }
        {
            int kk = tid & 31, jr = tid >> 5;
#pragma unroll
            for (int p = 0; p < 16; p++) {
                int jj = jr + p * 8;
                W_sm[kk * 132 + jj] = Wout[(size_t)(j0 + jj) * K + k0 + kk];
            }
        }
        __syncthreads();
#pragma unroll 8
        for (int kk = 0; kk < 32; kk++) {
            float4 wv = *(const float4*)&W_sm[kk * 132 + jg * 4];
            float a0 = A_sm[kk * 33 + bg * 4 + 0];
            float a1 = A_sm[kk * 33 + bg * 4 + 1];
            float a2 = A_sm[kk * 33 + bg * 4 + 2];
            float a3 = A_sm[kk * 33 + bg * 4 + 3];
            acc[0][0] += a0 * wv.x; acc[0][1] += a0 * wv.y; acc[0][2] += a0 * wv.z; acc[0][3] += a0 * wv.w;
            acc[1][0] += a1 * wv.x; acc[1][1] += a1 * wv.y; acc[1][2] += a1 * wv.z; acc[1][3] += a1 * wv.w;
            acc[2][0] += a2 * wv.x; acc[2][1] += a2 * wv.y; acc[2][2] += a2 * wv.z; acc[2][3] += a2 * wv.w;
            acc[3][0] += a3 * wv.x; acc[3][1] += a3 * wv.y; acc[3][2] += a3 * wv.z; acc[3][3] += a3 * wv.w;
        }
        __syncthreads();
    }

#pragma unroll
    for (int q = 0; q < 4; q++) {
        int b = bg * 4 + q;
        float4 v = make_float4(acc[q][0], acc[q][1], acc[q][2], acc[q][3]);
        *(float4*)&dout[((size_t)b * Sc + t) * Oc + j0 + jg * 4] = v;
    }
}

// ---------------- persistent recurrence kernel ----------------
// 512 threads = 16 warps. DMA staging (cp.async.bulk) of h / r*h.
// Tiling: lane = (col cc_ = lane>>2 in [0,8), batch-octet bq = lane&3 in [0,4)).
// Each lane owns ONE column and EIGHT batches (8*bq..8*bq+7 -> 4 f32x2 accums).
//  - weight loads: lane-distributed float4 (8 cols x 16B, conflict-free via
//    WSTRIDE=1028 row padding)
//  - h loads: 2x ld.shared.v2.b64 per k row (batches 8bq..+7), 1 wavefront each
//  - fma.rn.f32x2: 4 per (col, 8 batches, k)
// Phase 1 (z,r: n1<=14 slots): warp = g1*8+kq1, g1 in {0,1} owns slots 8g1..+7,
// kq1 in [0,8) -> 128-k range. Phase 2 (g: n2<=7 slots): warp = kq2 in [0,16)
// -> 64-k range, lane col cc_ = slot. Cross-warp reduce via red_sm (stride 33,
// scalar stores land conflict-free: bank = (cc_+8bq+i) mod 32 is a permutation).
// Finalize warp w owns slot w in BOTH phases -> z/h_old carried in registers.
__global__ void __launch_bounds__(THREADS) recur_kernel(
    const float* __restrict__ Whz, const float* __restrict__ Whr,
    const float* __restrict__ Whg, int layer, float* __restrict__ dout,
    int c1, int c2)
{
    extern __shared__ float smem[];
    const int NB  = gridDim.x;
    const int bid = blockIdx.x;
    const int tid = threadIdx.x;
    const int warp = tid >> 5, lane = tid & 31;
    const int cc_ = lane >> 2, bq = lane & 3;

    float* buf    = smem;                             // [1024][32] h or r*h
    float* w_sm   = smem + Hc * Bc;                   // (c1+c2) rows x WSTRIDE
    float* red_sm = w_sm + (size_t)(c1 + c2) * WSTRIDE;
    const int redRows = (8 * c1 > 16 * c2) ? 8 * c1 : 16 * c2;
    float* mb_f   = red_sm + (size_t)redRows * 33;    // 8 mbarriers (64B)
    const unsigned mb0  = s2u(mb_f);                  // h chunks: mb0+q*8
    const unsigned mbr0 = mb0 + 32;                   // rh chunks: mbr0+q*8
    const unsigned bufa = s2u(buf);

    const int n1 = (2048 - bid + NB - 1) / NB;
    const int n2 = (1024 - bid + NB - 1) / NB;

    if (tid == 0) {
        for (int q = 0; q < 8; q++) mb_init(mb0 + q * 8);
        asm volatile("fence.proxy.async.shared::cta;" ::: "memory");
    }
    __syncthreads();

    // stage weights once (phase1: z rows then r rows; then g rows), padded rows
    for (int s = 0; s < n1; s++) {
        int c = bid + s * NB;
        const float4* src = (const float4*)((c < 1024) ? (Whz + (size_t)c * Hc)
                                                       : (Whr + (size_t)(c - 1024) * Hc));
        float4* dst = (float4*)(w_sm + (size_t)s * WSTRIDE);
        if (tid < 256) dst[tid] = src[tid];
    }
    for (int s = 0; s < n2; s++) {
        int j = bid + s * NB;
        const float4* src = (const float4*)(Whg + (size_t)j * Hc);
        float4* dst = (float4*)(w_sm + (size_t)(n1 + s) * WSTRIDE);
        if (tid < 256) dst[tid] = src[tid];
    }
    // zero h
    for (int i = bid * THREADS + tid; i < Hc * Bc; i += NB * THREADS)
        __stcg(&g_h[i], 0.0f);

    unsigned ep = ld_acq(&g_gen);
    ep++; grid_bar(bid, NB, ep);

    // kick off stage of h(-1) for step 0
    if (tid == 0) {
#pragma unroll
        for (int q = 0; q < 4; q++) {
            mb_expect(mb0 + q * 8, 32768u);
            g2s(bufa + q * 32768u, g_h + q * 8192, 32768u, mb0 + q * 8);
        }
    }

    // phase mappings
    const int g1  = warp >> 3, kq1 = warp & 7;       // phase1
    const int s1  = g1 * 8 + cc_;                    // this lane's phase1 slot
    const int kq2 = warp;                            // phase2
    const int s2  = cc_;                             // this lane's phase2 slot

    const float* wrow1 = w_sm + (size_t)((s1 < n1) ? s1 : 0) * WSTRIDE + kq1 * 128;
    const float* wrow2 = w_sm + (size_t)(n1 + ((s2 < n2) ? s2 : 0)) * WSTRIDE + kq2 * 64;

    float zv = 0.f, ho = 0.f;

    for (int t = 0; t < Sc; t++) {
        const unsigned par = (unsigned)(t & 1);

        // prefetch x-projection inputs for this step's finalize
        float px = 0.f, pg = 0.f;
        if (warp < n1) {
            int cc = bid + warp * NB;
            bool isz = (warp < n2);
            int j = isz ? cc : cc - 1024;
            px = isz ? __ldcg(&g_xz[((size_t)t * Hc + j) * Bc + lane])
                     : __ldcg(&g_xr[((size_t)t * Hc + j) * Bc + lane]);
        }
        if (warp < n2) {
            int j = bid + warp * NB;
            pg = __ldcg(&g_xg[((size_t)t * Hc + j) * Bc + lane]);
        }

        // ---- phase 1 partials: own col (s1), 8 batches, 128 k ----
        mb_wait(mb0 + (kq1 >> 1) * 8, par);
        {
            unsigned long long a01 = 0ull, a23 = 0ull, a45 = 0ull, a67 = 0ull;
            unsigned ha = bufa + (unsigned)(kq1 * 16384 + bq * 32);
            const float4* wv4 = (const float4*)wrow1;
#pragma unroll 2
            for (int k4 = 0; k4 < 32; k4++) {
                float4 wv = wv4[k4];
                unsigned long long h01, h23, h45, h67, wd;
                LDSV2B64(h01, h23, ha);       LDSV2B64(h45, h67, ha + 16);
                wd = dup2(wv.x);
                FMA2(a01, h01, wd); FMA2(a23, h23, wd); FMA2(a45, h45, wd); FMA2(a67, h67, wd);
                LDSV2B64(h01, h23, ha + 128); LDSV2B64(h45, h67, ha + 144);
                wd = dup2(wv.y);
                FMA2(a01, h01, wd); FMA2(a23, h23, wd); FMA2(a45, h45, wd); FMA2(a67, h67, wd);
                LDSV2B64(h01, h23, ha + 256); LDSV2B64(h45, h67, ha + 272);
                wd = dup2(wv.z);
                FMA2(a01, h01, wd); FMA2(a23, h23, wd); FMA2(a45, h45, wd); FMA2(a67, h67, wd);
                LDSV2B64(h01, h23, ha + 384); LDSV2B64(h45, h67, ha + 400);
                wd = dup2(wv.w);
                FMA2(a01, h01, wd); FMA2(a23, h23, wd); FMA2(a45, h45, wd); FMA2(a67, h67, wd);
                ha += 512;
            }
            if (s1 < n1) {
                unsigned r0, r1;
                float* rp = red_sm + (size_t)(kq1 * c1 + s1) * 33 + 8 * bq;
                UNPK2(r0, r1, a01); rp[0] = __uint_as_float(r0); rp[1] = __uint_as_float(r1);
                UNPK2(r0, r1, a23); rp[2] = __uint_as_float(r0); rp[3] = __uint_as_float(r1);
                UNPK2(r0, r1, a45); rp[4] = __uint_as_float(r0); rp[5] = __uint_as_float(r1);
                UNPK2(r0, r1, a67); rp[6] = __uint_as_float(r0); rp[7] = __uint_as_float(r1);
            }
        }
        __syncthreads();

        // finalize phase 1: warp w -> slot w
        if (warp < n1) {
            int cc = bid + warp * NB;
            bool isz = (warp < n2);
            int j = isz ? cc : cc - 1024;
            float acc = px;
#pragma unroll
            for (int p = 0; p < 8; p++)
                acc += red_sm[(size_t)(p * c1 + warp) * 33 + lane];
            float val = sigm(acc);
            float hv = buf[j * Bc + lane];
            if (isz) { zv = val; ho = hv; }
            else     { __stcg(&g_rh[j * Bc + lane], val * hv); }
        }
        ep++; grid_bar(bid, NB, ep);

        // kick off stage of r*h (overwrites buf; all P1 reads done at grid_bar)
        if (tid == 0) {
#pragma unroll
            for (int q = 0; q < 4; q++) {
                mb_expect(mbr0 + q * 8, 32768u);
                g2s(bufa + q * 32768u, g_rh + q * 8192, 32768u, mbr0 + q * 8);
            }
        }

        // ---- phase 2 partials: own col (s2), 8 batches, 64 k ----
        mb_wait(mbr0 + (kq2 >> 2) * 8, par);
        {
            unsigned long long a01 = 0ull, a23 = 0ull, a45 = 0ull, a67 = 0ull;
            unsigned ha = bufa + (unsigned)(kq2 * 8192 + bq * 32);
            const float4* wv4 = (const float4*)wrow2;
#pragma unroll 2
            for (int k4 = 0; k4 < 16; k4++) {
                float4 wv = wv4[k4];
                unsigned long long h01, h23, h45, h67, wd;
                LDSV2B64(h01, h23, ha);       LDSV2B64(h45, h67, ha + 16);
                wd = dup2(wv.x);
                FMA2(a01, h01, wd); FMA2(a23, h23, wd); FMA2(a45, h45, wd); FMA2(a67, h67, wd);
                LDSV2B64(h01, h23, ha + 128); LDSV2B64(h45, h67, ha + 144);
                wd = dup2(wv.y);
                FMA2(a01, h01, wd); FMA2(a23, h23, wd); FMA2(a45, h45, wd); FMA2(a67, h67, wd);
                LDSV2B64(h01, h23, ha + 256); LDSV2B64(h45, h67, ha + 272);
                wd = dup2(wv.z);
                FMA2(a01, h01, wd); FMA2(a23, h23, wd); FMA2(a45, h45, wd); FMA2(a67, h67, wd);
                LDSV2B64(h01, h23, ha + 384); LDSV2B64(h45, h67, ha + 400);
                wd = dup2(wv.w);
                FMA2(a01, h01, wd); FMA2(a23, h23, wd); FMA2(a45, h45, wd); FMA2(a67, h67, wd);
                ha += 512;
            }
            if (s2 < n2) {
                unsigned r0, r1;
                float* rp = red_sm + (size_t)(kq2 * c2 + s2) * 33 + 8 * bq;
                UNPK2(r0, r1, a01); rp[0] = __uint_as_float(r0); rp[1] = __uint_as_float(r1);
                UNPK2(r0, r1, a23); rp[2] = __uint_as_float(r0); rp[3] = __uint_as_float(r1);
                UNPK2(r0, r1, a45); rp[4] = __uint_as_float(r0); rp[5] = __uint_as_float(r1);
                UNPK2(r0, r1, a67); rp[6] = __uint_as_float(r0); rp[7] = __uint_as_float(r1);
            }
        }
        __syncthreads();

        // finalize phase 2: warp w -> slot w (same slot as its phase-1 z)
        if (warp < n2) {
            int j = bid + warp * NB;
            float acc = pg;
#pragma unroll
            for (int p = 0; p < 16; p++)
                acc += red_sm[(size_t)(p * c2 + warp) * 33 + lane];
            float gg = fast_tanh(acc);
            float hn = zv * ho + (1.0f - zv) * gg;
            __stcg(&g_h[j * Bc + lane], hn);
            g_y[((size_t)t * Hc + j) * Bc + lane] = hn;
        }
        ep++; grid_bar(bid, NB, ep);

        // kick off stage of h(t) for step t+1 (overwrites buf; P2 reads done)
        if (tid == 0 && t + 1 < Sc) {
#pragma unroll
            for (int q = 0; q < 4; q++) {
                mb_expect(mb0 + q * 8, 32768u);
                g2s(bufa + q * 32768u, g_h + q * 8192, 32768u, mb0 + q * 8);
            }
        }
    }

    // write final hidden state for this layer: d_out[HID_OFF + b*2H + layer*H + j]
    for (int s = warp; s < n2; s += 16) {
        int j = bid + s * NB;
        dout[HID_OFF + (size_t)lane * (2 * Hc) + (size_t)layer * Hc + j] =
            __ldcg(&g_h[j * Bc + lane]);
    }
}

// ---------------- host ----------------
extern "C" void kernel_launch(void* const* d_in, const int* in_sizes, int n_in,
                              void* d_out, int out_size) {
    const float* x    = (const float*)d_in[0];
    const float* Wxz0 = (const float*)d_in[1];
    const float* bxz0 = (const float*)d_in[2];
    const float* Whz0 = (const float*)d_in[3];
    const float* Wxr0 = (const float*)d_in[4];
    const float* bxr0 = (const float*)d_in[5];
    const float* Whr0 = (const float*)d_in[6];
    const float* Wxg0 = (const float*)d_in[7];
    const float* bxg0 = (const float*)d_in[8];
    const float* Whg0 = (const float*)d_in[9];
    const float* Wxz1 = (const float*)d_in[10];
    const float* bxz1 = (const float*)d_in[11];
    const float* Whz1 = (const float*)d_in[12];
    const float* Wxr1 = (const float*)d_in[13];
    const float* bxr1 = (const float*)d_in[14];
    const float* Whr1 = (const float*)d_in[15];
    const float* Wxg1 = (const float*)d_in[16];
    const float* bxg1 = (const float*)d_in[17];
    const float* Whg1 = (const float*)d_in[18];
    const float* Wout = (const float*)d_in[19];
    const float* bout = (const float*)d_in[20];
    float* out = (float*)d_out;

    int dev = 0;
    cudaGetDevice(&dev);
    int sm = 148;
    cudaDeviceGetAttribute(&sm, cudaDevAttrMultiProcessorCount, dev);
    int NB = (sm < 148) ? sm : 148;
    int c1 = (2048 + NB - 1) / NB;           // phase1 slot capacity (<=14 for NB=148)
    int c2 = (1024 + NB - 1) / NB;           // phase2 slot capacity (<=7)
    int redRows = (8 * c1 > 16 * c2) ? 8 * c1 : 16 * c2;
    size_t smemB = ((size_t)Hc * Bc + (size_t)(c1 + c2) * WSTRIDE
                    + (size_t)redRows * 33 + 32) * sizeof(float);
    cudaFuncSetAttribute(recur_kernel, cudaFuncAttributeMaxDynamicSharedMemorySize, (int)smemB);

    dim3 pg(Sc, Hc / 128, 3);

    // Layer 0
    proj_kernel<<<pg, 256>>>(x, Wxz0, bxz0, Wxr0, bxr0, Wxg0, bxg0, Ic, 0);
    recur_kernel<<<NB, THREADS, smemB>>>(Whz0, Whr0, Whg0, 0, out, c1, c2);
    // Layer 1 (input projections read g_y written by layer-0 recurrence)
    proj_kernel<<<pg, 256>>>(x, Wxz1, bxz1, Wxr1, bxr1, Wxg1, bxg1, Hc, 1);
    recur_kernel<<<NB, THREADS, smemB>>>(Whz1, Whr1, Whg1, 1, out, c1, c2);
    // Output projection
    dim3 og(Sc, Oc / 128, 1);
    outproj_kernel<<<og, 256>>>(Wout, bout, out);
}

// round 8
// speedup vs baseline: 1.1022x; 1.1022x over previous
#include <cuda_runtime.h>
#include <cuda_bf16.h>
#include <math.h>

// Problem dims
#define Bc 32
#define Sc 512
#define Ic 256
#define Hc 1024
#define Oc 256
#define HID_OFF (Bc*Sc*Oc)   // floats: out (B,S,O) first, then hidden (B,2,H)
#define THREADS 1024
#define NWARPS 32
#define REDROWS (4*(NWARPS-4))   // 112 rows x 32 floats

// ---------------- scratch (__device__ globals: allocation-free) ----------------
// layout of all [S][H][B] tensors: idx = (t*Hc + j)*Bc + b
__device__ float g_xz[Sc*Hc*Bc];
__device__ float g_xr[Sc*Hc*Bc];
__device__ float g_xg[Sc*Hc*Bc];
__device__ float g_y [Sc*Hc*Bc];
__device__ float g_h [Hc*Bc];    // [j][b]
__device__ float g_rh[Hc*Bc];    // [j][b]

// ---------------- two-level grid barrier state ----------------
__device__ unsigned g_sub[16];
__device__ unsigned g_master;
__device__ unsigned g_gen;

__device__ __forceinline__ unsigned ld_acq(const unsigned* p) {
    unsigned v;
    asm volatile("ld.acquire.gpu.u32 %0, [%1];" : "=r"(v) : "l"(p) : "memory");
    return v;
}
__device__ __forceinline__ void st_rel(unsigned* p, unsigned v) {
    asm volatile("st.release.gpu.u32 [%0], %1;" :: "l"(p), "r"(v) : "memory");
}
__device__ __forceinline__ void st_rlx(unsigned* p, unsigned v) {
    asm volatile("st.relaxed.gpu.u32 [%0], %1;" :: "l"(p), "r"(v) : "memory");
}
__device__ __forceinline__ unsigned atom_add_acqrel(unsigned* p, unsigned v) {
    unsigned o;
    asm volatile("atom.add.acq_rel.gpu.u32 %0, [%1], %2;" : "=r"(o) : "l"(p), "r"(v) : "memory");
    return o;
}

// All blocks must call with the same monotonically increasing target.
__device__ __forceinline__ void grid_bar(int bid, int NB, unsigned target) {
    __syncthreads();
    if (threadIdx.x == 0) {
        int s = bid & 15;
        unsigned quota = (unsigned)((NB - 1 - s) / 16 + 1);
        unsigned o = atom_add_acqrel(&g_sub[s], 1u);
        if (o == quota - 1u) {
            st_rlx(&g_sub[s], 0u);
            unsigned nsub = (unsigned)((NB < 16) ? NB : 16);
            unsigned m = atom_add_acqrel(&g_master, 1u);
            if (m == nsub - 1u) {
                st_rlx(&g_master, 0u);
                st_rel(&g_gen, target);
            }
        }
        while ((int)(ld_acq(&g_gen) - target) < 0) { }
    }
    __syncthreads();
}

__device__ __forceinline__ float sigm(float x) {
    return 1.0f / (1.0f + __expf(-x));
}
__device__ __forceinline__ float fast_tanh(float x) {
    float ax = fabsf(x);
    float e = __expf(2.0f * ax);
    float t = 1.0f - 2.0f / (e + 1.0f);   // e=inf -> 1
    return copysignf(t, x);
}

// ---------------- mbarrier + bulk-copy helpers ----------------
__device__ __forceinline__ unsigned s2u(const void* p) {
    unsigned a;
    asm("{ .reg .u64 t; cvta.to.shared.u64 t, %1; cvt.u32.u64 %0, t; }" : "=r"(a) : "l"(p));
    return a;
}
__device__ __forceinline__ void mb_init(unsigned a) {
    asm volatile("mbarrier.init.shared.b64 [%0], 1;" :: "r"(a) : "memory");
}
__device__ __forceinline__ void mb_expect(unsigned a, unsigned bytes) {
    asm volatile("mbarrier.arrive.expect_tx.shared.b64 _, [%0], %1;" :: "r"(a), "r"(bytes) : "memory");
}
__device__ __forceinline__ void g2s(unsigned dst, const float* src, unsigned bytes, unsigned mb) {
    asm volatile("cp.async.bulk.shared::cta.global.mbarrier::complete_tx::bytes [%0], [%1], %2, [%3];"
                 :: "r"(dst), "l"(src), "r"(bytes), "r"(mb) : "memory");
}
__device__ __forceinline__ void mb_wait(unsigned a, unsigned parity) {
    unsigned done;
    asm volatile("{\n\t.reg .pred p;\n\t"
                 "mbarrier.try_wait.parity.acquire.cta.shared::cta.b64 p, [%1], %2;\n\t"
                 "selp.b32 %0, 1, 0, p;\n\t}"
                 : "=r"(done) : "r"(a), "r"(parity) : "memory");
    while (!done) {
        asm volatile("{\n\t.reg .pred p;\n\t"
                     "mbarrier.try_wait.parity.acquire.cta.shared::cta.b64 p, [%1], %2, 0x989680;\n\t"
                     "selp.b32 %0, 1, 0, p;\n\t}"
                     : "=r"(done) : "r"(a), "r"(parity) : "memory");
    }
}

// ---------------- input projection GEMM ----------------
__global__ void __launch_bounds__(256) proj_kernel(
    const float* __restrict__ X,
    const float* __restrict__ W0, const float* __restrict__ bv0,
    const float* __restrict__ W1, const float* __restrict__ bv1,
    const float* __restrict__ W2, const float* __restrict__ bv2,
    int K, int alayout)
{
    __shared__ float A_sm[32 * 33];
    __shared__ float W_sm[32 * 132];

    const int t = blockIdx.x;
    const int j0 = blockIdx.y * 128;
    const int gate = blockIdx.z;
    const float* W    = (gate == 0) ? W0  : (gate == 1) ? W1  : W2;
    const float* bias = (gate == 0) ? bv0 : (gate == 1) ? bv1 : bv2;
    float* out        = (gate == 0) ? g_xz : (gate == 1) ? g_xr : g_xg;

    const int tid = threadIdx.x;
    const int jg = tid & 31;
    const int bg = tid >> 5;

    float acc[4][4];
#pragma unroll
    for (int jq = 0; jq < 4; jq++) {
        float bvv = bias[j0 + jg * 4 + jq];
        acc[0][jq] = bvv; acc[1][jq] = bvv; acc[2][jq] = bvv; acc[3][jq] = bvv;
    }

    for (int k0 = 0; k0 < K; k0 += 32) {
        if (alayout == 0) {
            int kk = tid & 31, br = tid >> 5;
#pragma unroll
            for (int p = 0; p < 4; p++) {
                int b = br + p * 8;
                A_sm[kk * 33 + b] = X[((size_t)b * Sc + t) * K + k0 + kk];
            }
        } else {
            int b = tid & 31, kr = tid >> 5;
#pragma unroll
            for (int p = 0; p < 4; p++) {
                int kk = kr + p * 8;
                A_sm[kk * 33 + b] = g_y[((size_t)t * K + k0 + kk) * Bc + b];
            }
        }
        {
            int kk = tid & 31, jr = tid >> 5;
#pragma unroll
            for (int p = 0; p < 16; p++) {
                int jj = jr + p * 8;
                W_sm[kk * 132 + jj] = W[(size_t)(j0 + jj) * K + k0 + kk];
            }
        }
        __syncthreads();

#pragma unroll 8
        for (int kk = 0; kk < 32; kk++) {
            float4 wv = *(const float4*)&W_sm[kk * 132 + jg * 4];
            float a0 = A_sm[kk * 33 + bg * 4 + 0];
            float a1 = A_sm[kk * 33 + bg * 4 + 1];
            float a2 = A_sm[kk * 33 + bg * 4 + 2];
            float a3 = A_sm[kk * 33 + bg * 4 + 3];
            acc[0][0] += a0 * wv.x; acc[0][1] += a0 * wv.y; acc[0][2] += a0 * wv.z; acc[0][3] += a0 * wv.w;
            acc[1][0] += a1 * wv.x; acc[1][1] += a1 * wv.y; acc[1][2] += a1 * wv.z; acc[1][3] += a1 * wv.w;
            acc[2][0] += a2 * wv.x; acc[2][1] += a2 * wv.y; acc[2][2] += a2 * wv.z; acc[2][3] += a2 * wv.w;
            acc[3][0] += a3 * wv.x; acc[3][1] += a3 * wv.y; acc[3][2] += a3 * wv.z; acc[3][3] += a3 * wv.w;
        }
        __syncthreads();
    }

#pragma unroll
    for (int jq = 0; jq < 4; jq++) {
        int j = j0 + jg * 4 + jq;
        float4 v = make_float4(acc[0][jq], acc[1][jq], acc[2][jq], acc[3][jq]);
        *(float4*)&out[((size_t)t * Hc + j) * Bc + bg * 4] = v;
    }
}

// ---------------- output projection ----------------
__global__ void __launch_bounds__(256) outproj_kernel(
    const float* __restrict__ Wout, const float* __restrict__ bout,
    float* __restrict__ dout)
{
    __shared__ float A_sm[32 * 33];
    __shared__ float W_sm[32 * 132];

    const int t = blockIdx.x;
    const int j0 = blockIdx.y * 128;
    const int tid = threadIdx.x;
    const int jg = tid & 31;
    const int bg = tid >> 5;
    const int K = Hc;

    float acc[4][4];
#pragma unroll
    for (int jq = 0; jq < 4; jq++) {
        float bvv = bout[j0 + jg * 4 + jq];
        acc[0][jq] = bvv; acc[1][jq] = bvv; acc[2][jq] = bvv; acc[3][jq] = bvv;
    }

    for (int k0 = 0; k0 < K; k0 += 32) {
        {
            int b = tid & 31, kr = tid >> 5;
#pragma unroll
            for (int p = 0; p < 4; p++) {
                int kk = kr + p * 8;
                A_sm[kk * 33 + b] = g_y[((size_t)t * K + k0 + kk) * Bc + b];
            }
        }
        {
            int kk = tid & 31, jr = tid >> 5;
#pragma unroll
            for (int p = 0; p < 16; p++) {
                int jj = jr + p * 8;
                W_sm[kk * 132 + jj] = Wout[(size_t)(j0 + jj) * K + k0 + kk];
            }
        }
        __syncthreads();
#pragma unroll 8
        for (int kk = 0; kk < 32; kk++) {
            float4 wv = *(const float4*)&W_sm[kk * 132 + jg * 4];
            float a0 = A_sm[kk * 33 + bg * 4 + 0];
            float a1 = A_sm[kk * 33 + bg * 4 + 1];
            float a2 = A_sm[kk * 33 + bg * 4 + 2];
            float a3 = A_sm[kk * 33 + bg * 4 + 3];
            acc[0][0] += a0 * wv.x; acc[0][1] += a0 * wv.y; acc[0][2] += a0 * wv.z; acc[0][3] += a0 * wv.w;
            acc[1][0] += a1 * wv.x; acc[1][1] += a1 * wv.y; acc[1][2] += a1 * wv.z; acc[1][3] += a1 * wv.w;
            acc[2][0] += a2 * wv.x; acc[2][1] += a2 * wv.y; acc[2][2] += a2 * wv.z; acc[2][3] += a2 * wv.w;
            acc[3][0] += a3 * wv.x; acc[3][1] += a3 * wv.y; acc[3][2] += a3 * wv.z; acc[3][3] += a3 * wv.w;
        }
        __syncthreads();
    }

#pragma unroll
    for (int q = 0; q < 4; q++) {
        int b = bg * 4 + q;
        float4 v = make_float4(acc[q][0], acc[q][1], acc[q][2], acc[q][3]);
        *(float4*)&dout[((size_t)b * Sc + t) * Oc + j0 + jg * 4] = v;
    }
}

// ---------------- persistent recurrence kernel ----------------
// 1024 threads = 32 warps (occ 50%). Same compute scheme as the proven R4
// kernel (lane=batch scalar h loads, broadcast float4 weight loads), with
// k-splits doubled in phase 1 to use the extra warps:
// Phase 1 (z,r: n1<=14 slots): warp w -> colgroup g1=w&3 (slots 4g1..+3),
// k-eighth kq1=w>>2 in [0,8) -> 128 k each. Partial stores (kq1>0) at
// red row (w-4)*4+c; finalize warps 0-3 sum 7 partials + own register.
// Phase 2 (g: n2<=7 slots): warps 0..15 only: g2=w&1, kq2=w>>1 in [0,8)
// -> 128 k each; stores (w>=2) at row (w-2)*4+c; finalize warps 0-1.
// Finalize warp for z-slot s == finalize warp for g-slot s -> z/h_old in regs.
// DMA staging of h / r*h via cp.async.bulk in 4x32KB chunks + mbarriers.
__global__ void __launch_bounds__(THREADS) recur_kernel(
    const float* __restrict__ Whz, const float* __restrict__ Whr,
    const float* __restrict__ Whg, int layer, float* __restrict__ dout,
    int c1, int c2)
{
    extern __shared__ float smem[];
    const int NB  = gridDim.x;
    const int bid = blockIdx.x;
    const int tid = threadIdx.x;
    const int warp = tid >> 5, lane = tid & 31;

    float* buf    = smem;                           // [1024][32] h or r*h
    float* w_sm   = smem + Hc * Bc;                 // (c1+c2) rows x 1024
    float* red_sm = w_sm + (size_t)(c1 + c2) * Hc;  // REDROWS x 32
    float* mb_f   = red_sm + REDROWS * 32;          // 8 mbarriers (64B)
    const unsigned mb0  = s2u(mb_f);                // h chunks: mb0+q*8
    const unsigned mbr0 = mb0 + 32;                 // rh chunks: mbr0+q*8
    const unsigned bufa = s2u(buf);

    const int n1 = (2048 - bid + NB - 1) / NB;
    const int n2 = (1024 - bid + NB - 1) / NB;

    if (tid == 0) {
        for (int q = 0; q < 8; q++) mb_init(mb0 + q * 8);
        asm volatile("fence.proxy.async.shared::cta;" ::: "memory");
    }
    __syncthreads();

    // stage weights once (phase1: z rows then r rows; then g rows)
    for (int s = 0; s < n1; s++) {
        int c = bid + s * NB;
        const float4* src = (const float4*)((c < 1024) ? (Whz + (size_t)c * Hc)
                                                       : (Whr + (size_t)(c - 1024) * Hc));
        float4* dst = (float4*)(w_sm + (size_t)s * Hc);
        if (tid < 256) dst[tid] = src[tid];
    }
    for (int s = 0; s < n2; s++) {
        int j = bid + s * NB;
        const float4* src = (const float4*)(Whg + (size_t)j * Hc);
        float4* dst = (float4*)(w_sm + (size_t)(n1 + s) * Hc);
        if (tid < 256) dst[tid] = src[tid];
    }
    // zero h
    for (int i = bid * THREADS + tid; i < Hc * Bc; i += NB * THREADS)
        __stcg(&g_h[i], 0.0f);

    unsigned ep = ld_acq(&g_gen);
    ep++; grid_bar(bid, NB, ep);

    // kick off stage of h(-1) for step 0
    if (tid == 0) {
#pragma unroll
        for (int q = 0; q < 4; q++) {
            mb_expect(mb0 + q * 8, 32768u);
            g2s(bufa + q * 32768u, g_h + q * 8192, 32768u, mb0 + q * 8);
        }
    }

    const int g1 = warp & 3, kq1 = warp >> 2;     // phase1: kq1 in [0,8)
    const int g2v = warp & 1, kq2 = warp >> 1;    // phase2 (warps 0..15): kq2 in [0,8)

    const float4* wp10; const float4* wp11; const float4* wp12; const float4* wp13;
    {
        int s0 = 4 * g1;
        int a = (s0 + 0 < n1) ? s0 + 0 : 0;
        int b = (s0 + 1 < n1) ? s0 + 1 : 0;
        int c = (s0 + 2 < n1) ? s0 + 2 : 0;
        int d = (s0 + 3 < n1) ? s0 + 3 : 0;
        wp10 = (const float4*)(w_sm + (size_t)a * Hc + kq1 * 128);
        wp11 = (const float4*)(w_sm + (size_t)b * Hc + kq1 * 128);
        wp12 = (const float4*)(w_sm + (size_t)c * Hc + kq1 * 128);
        wp13 = (const float4*)(w_sm + (size_t)d * Hc + kq1 * 128);
    }
    const float4* wp20; const float4* wp21; const float4* wp22; const float4* wp23;
    {
        int s0 = 4 * g2v;
        int a = (s0 + 0 < n2) ? s0 + 0 : 0;
        int b = (s0 + 1 < n2) ? s0 + 1 : 0;
        int c = (s0 + 2 < n2) ? s0 + 2 : 0;
        int d = (s0 + 3 < n2) ? s0 + 3 : 0;
        wp20 = (const float4*)(w_sm + (size_t)(n1 + a) * Hc + kq2 * 128);
        wp21 = (const float4*)(w_sm + (size_t)(n1 + b) * Hc + kq2 * 128);
        wp22 = (const float4*)(w_sm + (size_t)(n1 + c) * Hc + kq2 * 128);
        wp23 = (const float4*)(w_sm + (size_t)(n1 + d) * Hc + kq2 * 128);
    }

    float zv0 = 0.f, zv1 = 0.f, zv2 = 0.f, zv3 = 0.f;
    float ho0 = 0.f, ho1 = 0.f, ho2 = 0.f, ho3 = 0.f;

    for (int t = 0; t < Sc; t++) {
        const unsigned par = (unsigned)(t & 1);

        // prefetch x-projection inputs for this step's finalize (L2-latency loads)
        float px0 = 0.f, px1 = 0.f, px2 = 0.f, px3 = 0.f;
        if (warp < 4) {
#pragma unroll
            for (int c = 0; c < 4; c++) {
                int s = 4 * warp + c;
                if (s < n1) {
                    int cc = bid + s * NB;
                    bool isz = (s < n2);
                    int j = isz ? cc : cc - 1024;
                    float v = isz ? __ldcg(&g_xz[((size_t)t * Hc + j) * Bc + lane])
                                  : __ldcg(&g_xr[((size_t)t * Hc + j) * Bc + lane]);
                    if (c == 0) px0 = v; else if (c == 1) px1 = v;
                    else if (c == 2) px2 = v; else px3 = v;
                }
            }
        }
        float pg0 = 0.f, pg1 = 0.f, pg2 = 0.f, pg3 = 0.f;
        if (warp < 2) {
#pragma unroll
            for (int c = 0; c < 4; c++) {
                int s = 4 * warp + c;
                if (s < n2) {
                    int j = bid + s * NB;
                    float v = __ldcg(&g_xg[((size_t)t * Hc + j) * Bc + lane]);
                    if (c == 0) pg0 = v; else if (c == 1) pg1 = v;
                    else if (c == 2) pg2 = v; else pg3 = v;
                }
            }
        }

        // ---- phase 1: wait own h chunk, partials (4 cols x 128 k per warp) ----
        mb_wait(mb0 + (kq1 >> 1) * 8, par);
        float a0 = 0.f, a1 = 0.f, a2 = 0.f, a3 = 0.f;
        {
            const float* hp = buf + kq1 * 128 * Bc + lane;
#pragma unroll 2
            for (int k4 = 0; k4 < 32; k4++) {
                float4 wa = wp10[k4]; float4 wb = wp11[k4];
                float4 wc = wp12[k4]; float4 wd = wp13[k4];
                float v0 = hp[0], v1 = hp[Bc], v2 = hp[2 * Bc], v3 = hp[3 * Bc];
                a0 += v0 * wa.x; a0 += v1 * wa.y; a0 += v2 * wa.z; a0 += v3 * wa.w;
                a1 += v0 * wb.x; a1 += v1 * wb.y; a1 += v2 * wb.z; a1 += v3 * wb.w;
                a2 += v0 * wc.x; a2 += v1 * wc.y; a2 += v2 * wc.z; a2 += v3 * wc.w;
                a3 += v0 * wd.x; a3 += v1 * wd.y; a3 += v2 * wd.z; a3 += v3 * wd.w;
                hp += 4 * Bc;
            }
        }
        if (kq1 > 0) {
            float* rp = red_sm + (size_t)((warp - 4) * 4) * 32 + lane;
            rp[0]  = a0;
            rp[32] = a1;
            rp[64] = a2;
            rp[96] = a3;
        }
        __syncthreads();

        // finalize phase 1: warp w (<4) -> slots 4w..4w+3
        if (warp < 4) {
#pragma unroll
            for (int c = 0; c < 4; c++) {
                int s = 4 * warp + c;
                if (s < n1) {
                    int cc = bid + s * NB;
                    bool isz = (s < n2);
                    int j = isz ? cc : cc - 1024;
                    float acc = (c == 0) ? a0 : (c == 1) ? a1 : (c == 2) ? a2 : a3;
#pragma unroll
                    for (int p = 1; p < 8; p++)
                        acc += red_sm[(size_t)((warp + 4 * p - 4) * 4 + c) * 32 + lane];
                    float xin = (c == 0) ? px0 : (c == 1) ? px1 : (c == 2) ? px2 : px3;
                    float val = sigm(acc + xin);
                    float hv = buf[j * Bc + lane];
                    if (isz) {
                        if (c == 0) { zv0 = val; ho0 = hv; }
                        else if (c == 1) { zv1 = val; ho1 = hv; }
                        else if (c == 2) { zv2 = val; ho2 = hv; }
                        else { zv3 = val; ho3 = hv; }
                    } else {
                        __stcg(&g_rh[j * Bc + lane], val * hv);
                    }
                }
            }
        }
        ep++; grid_bar(bid, NB, ep);

        // kick off stage of r*h (overwrites buf; all P1 reads done at grid_bar)
        if (tid == 0) {
#pragma unroll
            for (int q = 0; q < 4; q++) {
                mb_expect(mbr0 + q * 8, 32768u);
                g2s(bufa + q * 32768u, g_rh + q * 8192, 32768u, mbr0 + q * 8);
            }
        }

        // ---- phase 2 (warps 0..15): wait own rh chunk, partials (4 cols x 128 k) ----
        float b0 = 0.f, b1 = 0.f, b2 = 0.f, b3 = 0.f;
        if (warp < 16) {
            mb_wait(mbr0 + (kq2 >> 1) * 8, par);
            const float* hp = buf + kq2 * 128 * Bc + lane;
#pragma unroll 2
            for (int k4 = 0; k4 < 32; k4++) {
                float4 wa = wp20[k4]; float4 wb = wp21[k4];
                float4 wc = wp22[k4]; float4 wd = wp23[k4];
                float v0 = hp[0], v1 = hp[Bc], v2 = hp[2 * Bc], v3 = hp[3 * Bc];
                b0 += v0 * wa.x; b0 += v1 * wa.y; b0 += v2 * wa.z; b0 += v3 * wa.w;
                b1 += v0 * wb.x; b1 += v1 * wb.y; b1 += v2 * wb.z; b1 += v3 * wb.w;
                b2 += v0 * wc.x; b2 += v1 * wc.y; b2 += v2 * wc.z; b2 += v3 * wc.w;
                b3 += v0 * wd.x; b3 += v1 * wd.y; b3 += v2 * wd.z; b3 += v3 * wd.w;
                hp += 4 * Bc;
            }
            if (warp >= 2) {
                float* rp = red_sm + (size_t)((warp - 2) * 4) * 32 + lane;
                rp[0]  = b0;
                rp[32] = b1;
                rp[64] = b2;
                rp[96] = b3;
            }
        }
        __syncthreads();

        // finalize phase 2: warp w (<2) -> slots 4w..4w+3 (same as its phase-1 z)
        if (warp < 2) {
#pragma unroll
            for (int c = 0; c < 4; c++) {
                int s = 4 * warp + c;
                if (s < n2) {
                    int j = bid + s * NB;
                    float acc = (c == 0) ? b0 : (c == 1) ? b1 : (c == 2) ? b2 : b3;
#pragma unroll
                    for (int p = 1; p < 8; p++)
                        acc += red_sm[(size_t)((warp + 2 * p - 2) * 4 + c) * 32 + lane];
                    float xin = (c == 0) ? pg0 : (c == 1) ? pg1 : (c == 2) ? pg2 : pg3;
                    float gg = fast_tanh(acc + xin);
                    float z  = (c == 0) ? zv0 : (c == 1) ? zv1 : (c == 2) ? zv2 : zv3;
                    float ho = (c == 0) ? ho0 : (c == 1) ? ho1 : (c == 2) ? ho2 : ho3;
                    float hn = z * ho + (1.0f - z) * gg;
                    __stcg(&g_h[j * Bc + lane], hn);
                    g_y[((size_t)t * Hc + j) * Bc + lane] = hn;
                }
            }
        }
        ep++; grid_bar(bid, NB, ep);

        // kick off stage of h(t) for step t+1 (overwrites buf; P2 reads done)
        if (tid == 0 && t + 1 < Sc) {
#pragma unroll
            for (int q = 0; q < 4; q++) {
                mb_expect(mb0 + q * 8, 32768u);
                g2s(bufa + q * 32768u, g_h + q * 8192, 32768u, mb0 + q * 8);
            }
        }
    }

    // write final hidden state for this layer: d_out[HID_OFF + b*2H + layer*H + j]
    for (int s = warp; s < n2; s += NWARPS) {
        int j = bid + s * NB;
        dout[HID_OFF + (size_t)lane * (2 * Hc) + (size_t)layer * Hc + j] =
            __ldcg(&g_h[j * Bc + lane]);
    }
}

// ---------------- host ----------------
extern "C" void kernel_launch(void* const* d_in, const int* in_sizes, int n_in,
                              void* d_out, int out_size) {
    const float* x    = (const float*)d_in[0];
    const float* Wxz0 = (const float*)d_in[1];
    const float* bxz0 = (const float*)d_in[2];
    const float* Whz0 = (const float*)d_in[3];
    const float* Wxr0 = (const float*)d_in[4];
    const float* bxr0 = (const float*)d_in[5];
    const float* Whr0 = (const float*)d_in[6];
    const float* Wxg0 = (const float*)d_in[7];
    const float* bxg0 = (const float*)d_in[8];
    const float* Whg0 = (const float*)d_in[9];
    const float* Wxz1 = (const float*)d_in[10];
    const float* bxz1 = (const float*)d_in[11];
    const float* Whz1 = (const float*)d_in[12];
    const float* Wxr1 = (const float*)d_in[13];
    const float* bxr1 = (const float*)d_in[14];
    const float* Whr1 = (const float*)d_in[15];
    const float* Wxg1 = (const float*)d_in[16];
    const float* bxg1 = (const float*)d_in[17];
    const float* Whg1 = (const float*)d_in[18];
    const float* Wout = (const float*)d_in[19];
    const float* bout = (const float*)d_in[20];
    float* out = (float*)d_out;

    int dev = 0;
    cudaGetDevice(&dev);
    int sm = 148;
    cudaDeviceGetAttribute(&sm, cudaDevAttrMultiProcessorCount, dev);
    int NB = (sm < 148) ? sm : 148;
    int c1 = (2048 + NB - 1) / NB;           // phase1 slot capacity (14 at NB=148)
    int c2 = (1024 + NB - 1) / NB;           // phase2 slot capacity (7)
    size_t smemB = ((size_t)Hc * Bc + (size_t)(c1 + c2) * Hc
                    + (size_t)REDROWS * 32 + 16) * sizeof(float);
    cudaFuncSetAttribute(recur_kernel, cudaFuncAttributeMaxDynamicSharedMemorySize, (int)smemB);

    dim3 pg(Sc, Hc / 128, 3);

    // Layer 0
    proj_kernel<<<pg, 256>>>(x, Wxz0, bxz0, Wxr0, bxr0, Wxg0, bxg0, Ic, 0);
    recur_kernel<<<NB, THREADS, smemB>>>(Whz0, Whr0, Whg0, 0, out, c1, c2);
    // Layer 1 (input projections read g_y written by layer-0 recurrence)
    proj_kernel<<<pg, 256>>>(x, Wxz1, bxz1, Wxr1, bxr1, Wxg1, bxg1, Hc, 1);
    recur_kernel<<<NB, THREADS, smemB>>>(Whz1, Whr1, Whg1, 1, out, c1, c2);
    // Output projection
    dim3 og(Sc, Oc / 128, 1);
    outproj_kernel<<<og, 256>>>(Wout, bout, out);
}

// round 9
// speedup vs baseline: 1.1256x; 1.0212x over previous
#include <cuda_runtime.h>
#include <cuda_bf16.h>
#include <math.h>

// Problem dims
#define Bc 32
#define Sc 512
#define Ic 256
#define Hc 1024
#define Oc 256
#define HID_OFF (Bc*Sc*Oc)   // floats: out (B,S,O) first, then hidden (B,2,H)
#define THREADS 512

// ---------------- scratch (__device__ globals: allocation-free) ----------------
// layout of all [S][H][B] tensors: idx = (t*Hc + j)*Bc + b
__device__ float g_xz[Sc*Hc*Bc];
__device__ float g_xr[Sc*Hc*Bc];
__device__ float g_xg[Sc*Hc*Bc];
__device__ float g_y [Sc*Hc*Bc];
__device__ float g_h [Hc*Bc];    // [j][b]
__device__ float g_rh[Hc*Bc];    // [j][b]

// ---------------- two-level grid barrier state ----------------
__device__ unsigned g_sub[16];
__device__ unsigned g_master;
__device__ unsigned g_gen;

__device__ __forceinline__ unsigned ld_acq(const unsigned* p) {
    unsigned v;
    asm volatile("ld.acquire.gpu.u32 %0, [%1];" : "=r"(v) : "l"(p) : "memory");
    return v;
}
__device__ __forceinline__ void st_rel(unsigned* p, unsigned v) {
    asm volatile("st.release.gpu.u32 [%0], %1;" :: "l"(p), "r"(v) : "memory");
}
__device__ __forceinline__ void st_rlx(unsigned* p, unsigned v) {
    asm volatile("st.relaxed.gpu.u32 [%0], %1;" :: "l"(p), "r"(v) : "memory");
}
__device__ __forceinline__ unsigned atom_add_acqrel(unsigned* p, unsigned v) {
    unsigned o;
    asm volatile("atom.add.acq_rel.gpu.u32 %0, [%1], %2;" : "=r"(o) : "l"(p), "r"(v) : "memory");
    return o;
}

// All blocks must call with the same monotonically increasing target.
__device__ __forceinline__ void grid_bar(int bid, int NB, unsigned target) {
    __syncthreads();
    if (threadIdx.x == 0) {
        int s = bid & 15;
        unsigned quota = (unsigned)((NB - 1 - s) / 16 + 1);
        unsigned o = atom_add_acqrel(&g_sub[s], 1u);
        if (o == quota - 1u) {
            st_rlx(&g_sub[s], 0u);
            unsigned nsub = (unsigned)((NB < 16) ? NB : 16);
            unsigned m = atom_add_acqrel(&g_master, 1u);
            if (m == nsub - 1u) {
                st_rlx(&g_master, 0u);
                st_rel(&g_gen, target);
            }
        }
        while ((int)(ld_acq(&g_gen) - target) < 0) { }
    }
    __syncthreads();
}

__device__ __forceinline__ float sigm(float x) {
    return 1.0f / (1.0f + __expf(-x));
}
__device__ __forceinline__ float fast_tanh(float x) {
    float ax = fabsf(x);
    float e = __expf(2.0f * ax);
    float t = 1.0f - 2.0f / (e + 1.0f);   // e=inf -> 1
    return copysignf(t, x);
}

// ---------------- mbarrier + bulk-copy helpers ----------------
__device__ __forceinline__ unsigned s2u(const void* p) {
    unsigned a;
    asm("{ .reg .u64 t; cvta.to.shared.u64 t, %1; cvt.u32.u64 %0, t; }" : "=r"(a) : "l"(p));
    return a;
}
__device__ __forceinline__ void mb_init(unsigned a) {
    asm volatile("mbarrier.init.shared.b64 [%0], 1;" :: "r"(a) : "memory");
}
__device__ __forceinline__ void mb_expect(unsigned a, unsigned bytes) {
    asm volatile("mbarrier.arrive.expect_tx.shared.b64 _, [%0], %1;" :: "r"(a), "r"(bytes) : "memory");
}
__device__ __forceinline__ void g2s(unsigned dst, const float* src, unsigned bytes, unsigned mb) {
    asm volatile("cp.async.bulk.shared::cta.global.mbarrier::complete_tx::bytes [%0], [%1], %2, [%3];"
                 :: "r"(dst), "l"(src), "r"(bytes), "r"(mb) : "memory");
}
__device__ __forceinline__ void mb_wait(unsigned a, unsigned parity) {
    unsigned done;
    asm volatile("{\n\t.reg .pred p;\n\t"
                 "mbarrier.try_wait.parity.acquire.cta.shared::cta.b64 p, [%1], %2;\n\t"
                 "selp.b32 %0, 1, 0, p;\n\t}"
                 : "=r"(done) : "r"(a), "r"(parity) : "memory");
    while (!done) {
        asm volatile("{\n\t.reg .pred p;\n\t"
                     "mbarrier.try_wait.parity.acquire.cta.shared::cta.b64 p, [%1], %2, 0x989680;\n\t"
                     "selp.b32 %0, 1, 0, p;\n\t}"
                     : "=r"(done) : "r"(a), "r"(parity) : "memory");
    }
}

// packed f32x2 helpers
__device__ __forceinline__ unsigned long long dup2(float w) {
    unsigned long long d;
    unsigned r = __float_as_uint(w);
    asm("mov.b64 %0, {%1, %1};" : "=l"(d) : "r"(r));
    return d;
}
#define FMA2(acc, h, w) asm("fma.rn.f32x2 %0, %1, %2, %0;" : "+l"(acc) : "l"(h), "l"(w))
#define LDSV2B64(h01, h23, addr) \
    asm("ld.shared.v2.b64 {%0, %1}, [%2];" : "=l"(h01), "=l"(h23) : "r"(addr))
#define UNPK2(r0, r1, a) asm("mov.b64 {%0, %1}, %2;" : "=r"(r0), "=r"(r1) : "l"(a))

// ---------------- input projection GEMM (f32x2 packed) ----------------
// out_gate[t][j][b] = bias[j] + sum_k A[b,t,k] (or g_y[t][k][b]) * W[j][k]
// grid: (S, H/128, 3 gates), block 256. Thread (jg,bg): 4 j x 4 b outputs,
// batch-paired in 8 packed f32x2 accumulators. A_sm rows padded to 36 floats
// (144B, 16B-aligned) so the b-quad loads as one broadcast ld.shared.v2.b64.
__global__ void __launch_bounds__(256) proj_kernel(
    const float* __restrict__ X,
    const float* __restrict__ W0, const float* __restrict__ bv0,
    const float* __restrict__ W1, const float* __restrict__ bv1,
    const float* __restrict__ W2, const float* __restrict__ bv2,
    int K, int alayout)
{
    __shared__ __align__(16) float A_sm[32 * 36];
    __shared__ __align__(16) float W_sm[32 * 132];

    const int t = blockIdx.x;
    const int j0 = blockIdx.y * 128;
    const int gate = blockIdx.z;
    const float* W    = (gate == 0) ? W0  : (gate == 1) ? W1  : W2;
    const float* bias = (gate == 0) ? bv0 : (gate == 1) ? bv1 : bv2;
    float* out        = (gate == 0) ? g_xz : (gate == 1) ? g_xr : g_xg;

    const int tid = threadIdx.x;
    const int jg = tid & 31;
    const int bg = tid >> 5;

    unsigned long long acc01[4], acc23[4];
#pragma unroll
    for (int jq = 0; jq < 4; jq++) {
        unsigned long long bv = dup2(bias[j0 + jg * 4 + jq]);
        acc01[jq] = bv; acc23[jq] = bv;
    }

    const unsigned aBase = s2u(A_sm) + (unsigned)(bg * 16);
    const unsigned wBase = s2u(W_sm) + (unsigned)(jg * 16);

    for (int k0 = 0; k0 < K; k0 += 32) {
        if (alayout == 0) {
            int kk = tid & 31, br = tid >> 5;
#pragma unroll
            for (int p = 0; p < 4; p++) {
                int b = br + p * 8;
                A_sm[kk * 36 + b] = X[((size_t)b * Sc + t) * K + k0 + kk];
            }
        } else {
            int b = tid & 31, kr = tid >> 5;
#pragma unroll
            for (int p = 0; p < 4; p++) {
                int kk = kr + p * 8;
                A_sm[kk * 36 + b] = g_y[((size_t)t * K + k0 + kk) * Bc + b];
            }
        }
        {
            int kk = tid & 31, jr = tid >> 5;
#pragma unroll
            for (int p = 0; p < 16; p++) {
                int jj = jr + p * 8;
                W_sm[kk * 132 + jj] = W[(size_t)(j0 + jj) * K + k0 + kk];
            }
        }
        __syncthreads();

#pragma unroll 8
        for (int kk = 0; kk < 32; kk++) {
            float4 wv = *(const float4*)(W_sm + kk * 132 + jg * 4);
            unsigned long long a01, a23;
            LDSV2B64(a01, a23, aBase + (unsigned)(kk * 144));
            unsigned long long w0 = dup2(wv.x), w1 = dup2(wv.y);
            unsigned long long w2 = dup2(wv.z), w3 = dup2(wv.w);
            FMA2(acc01[0], a01, w0); FMA2(acc23[0], a23, w0);
            FMA2(acc01[1], a01, w1); FMA2(acc23[1], a23, w1);
            FMA2(acc01[2], a01, w2); FMA2(acc23[2], a23, w2);
            FMA2(acc01[3], a01, w3); FMA2(acc23[3], a23, w3);
        }
        __syncthreads();
    }
    (void)wBase;

#pragma unroll
    for (int jq = 0; jq < 4; jq++) {
        int j = j0 + jg * 4 + jq;
        unsigned r0, r1, r2, r3;
        UNPK2(r0, r1, acc01[jq]);
        UNPK2(r2, r3, acc23[jq]);
        float4 v = make_float4(__uint_as_float(r0), __uint_as_float(r1),
                               __uint_as_float(r2), __uint_as_float(r3));
        *(float4*)&out[((size_t)t * Hc + j) * Bc + bg * 4] = v;
    }
}

// ---------------- output projection (f32x2 packed) ----------------
// out[b][t][o] = bout[o] + sum_h g_y[t][h][b] * Wout[o][h]
__global__ void __launch_bounds__(256) outproj_kernel(
    const float* __restrict__ Wout, const float* __restrict__ bout,
    float* __restrict__ dout)
{
    __shared__ __align__(16) float A_sm[32 * 36];
    __shared__ __align__(16) float W_sm[32 * 132];

    const int t = blockIdx.x;
    const int j0 = blockIdx.y * 128;
    const int tid = threadIdx.x;
    const int jg = tid & 31;
    const int bg = tid >> 5;
    const int K = Hc;

    unsigned long long acc01[4], acc23[4];
#pragma unroll
    for (int jq = 0; jq < 4; jq++) {
        unsigned long long bv = dup2(bout[j0 + jg * 4 + jq]);
        acc01[jq] = bv; acc23[jq] = bv;
    }

    const unsigned aBase = s2u(A_sm) + (unsigned)(bg * 16);

    for (int k0 = 0; k0 < K; k0 += 32) {
        {
            int b = tid & 31, kr = tid >> 5;
#pragma unroll
            for (int p = 0; p < 4; p++) {
                int kk = kr + p * 8;
                A_sm[kk * 36 + b] = g_y[((size_t)t * K + k0 + kk) * Bc + b];
            }
        }
        {
            int kk = tid & 31, jr = tid >> 5;
#pragma unroll
            for (int p = 0; p < 16; p++) {
                int jj = jr + p * 8;
                W_sm[kk * 132 + jj] = Wout[(size_t)(j0 + jj) * K + k0 + kk];
            }
        }
        __syncthreads();

#pragma unroll 8
        for (int kk = 0; kk < 32; kk++) {
            float4 wv = *(const float4*)(W_sm + kk * 132 + jg * 4);
            unsigned long long a01, a23;
            LDSV2B64(a01, a23, aBase + (unsigned)(kk * 144));
            unsigned long long w0 = dup2(wv.x), w1 = dup2(wv.y);
            unsigned long long w2 = dup2(wv.z), w3 = dup2(wv.w);
            FMA2(acc01[0], a01, w0); FMA2(acc23[0], a23, w0);
            FMA2(acc01[1], a01, w1); FMA2(acc23[1], a23, w1);
            FMA2(acc01[2], a01, w2); FMA2(acc23[2], a23, w2);
            FMA2(acc01[3], a01, w3); FMA2(acc23[3], a23, w3);
        }
        __syncthreads();
    }

    // unpack: value for (jq, b) with b = bg*4 + {0,1,2,3}
    float vals[4][4];
#pragma unroll
    for (int jq = 0; jq < 4; jq++) {
        unsigned r0, r1, r2, r3;
        UNPK2(r0, r1, acc01[jq]);
        UNPK2(r2, r3, acc23[jq]);
        vals[jq][0] = __uint_as_float(r0); vals[jq][1] = __uint_as_float(r1);
        vals[jq][2] = __uint_as_float(r2); vals[jq][3] = __uint_as_float(r3);
    }
#pragma unroll
    for (int q = 0; q < 4; q++) {
        int b = bg * 4 + q;
        float4 v = make_float4(vals[0][q], vals[1][q], vals[2][q], vals[3][q]);
        *(float4*)&dout[((size_t)b * Sc + t) * Oc + j0 + jg * 4] = v;
    }
}

// ---------------- persistent recurrence kernel (R4-proven, verbatim) ----------------
// 512 threads = 16 warps. DMA staging (cp.async.bulk) of h / r*h in 4x32KB
// chunks + mbarriers; warp with k-quarter kq waits only on chunk kq.
// Phase 1 (z,r: 2048 cols): warp w -> colgroup g1=w&3 (slots 4*g1..+3),
// k-quarter kq1=w>>2. Phase 2 (g: 1024 cols): g2=w&1, k-eighth kq2=w>>1.
// Cross-warp reduction via red_sm. Finalize warp for z-slot s == finalize
// warp for g-slot s -> z and h_old carried in registers.
__global__ void __launch_bounds__(THREADS) recur_kernel(
    const float* __restrict__ Whz, const float* __restrict__ Whr,
    const float* __restrict__ Whg, int layer, float* __restrict__ dout)
{
    extern __shared__ float smem[];
    const int NB  = gridDim.x;
    const int bid = blockIdx.x;
    const int tid = threadIdx.x;
    const int warp = tid >> 5, lane = tid & 31;

    const int slotsMax = (2048 + NB - 1) / NB + (1024 + NB - 1) / NB;
    float* buf    = smem;                          // [1024][32] h or r*h
    float* w_sm   = smem + Hc * Bc;                // slotsMax rows x 1024
    float* red_sm = w_sm + (size_t)slotsMax * Hc;  // 16*4*32
    float* mb_f   = red_sm + 16 * 4 * 32;          // 8 mbarriers (64B)
    const unsigned mb0  = s2u(mb_f);               // h chunks: mb0+q*8
    const unsigned mbr0 = mb0 + 32;                // rh chunks: mbr0+q*8
    const unsigned bufa = s2u(buf);

    const int n1 = (2048 - bid + NB - 1) / NB;
    const int n2 = (1024 - bid + NB - 1) / NB;

    if (tid == 0) {
        for (int q = 0; q < 8; q++) mb_init(mb0 + q * 8);
        asm volatile("fence.proxy.async.shared::cta;" ::: "memory");
    }
    __syncthreads();

    // stage weights once (phase1: z rows then r rows; then g rows)
    for (int s = 0; s < n1; s++) {
        int c = bid + s * NB;
        const float4* src = (const float4*)((c < 1024) ? (Whz + (size_t)c * Hc)
                                                       : (Whr + (size_t)(c - 1024) * Hc));
        float4* dst = (float4*)(w_sm + (size_t)s * Hc);
        if (tid < 256) dst[tid] = src[tid];
    }
    for (int s = 0; s < n2; s++) {
        int j = bid + s * NB;
        const float4* src = (const float4*)(Whg + (size_t)j * Hc);
        float4* dst = (float4*)(w_sm + (size_t)(n1 + s) * Hc);
        if (tid < 256) dst[tid] = src[tid];
    }
    // zero h
    for (int i = bid * THREADS + tid; i < Hc * Bc; i += NB * THREADS)
        __stcg(&g_h[i], 0.0f);

    unsigned ep = ld_acq(&g_gen);
    ep++; grid_bar(bid, NB, ep);

    // kick off stage of h(-1) for step 0
    if (tid == 0) {
#pragma unroll
        for (int q = 0; q < 4; q++) {
            mb_expect(mb0 + q * 8, 32768u);
            g2s(bufa + q * 32768u, g_h + q * 8192, 32768u, mb0 + q * 8);
        }
    }

    const int g1 = warp & 3, kq1 = warp >> 2;
    const int g2v = warp & 1, kq2 = warp >> 1;

    const float4* wp10; const float4* wp11; const float4* wp12; const float4* wp13;
    {
        int s0 = 4 * g1;
        int a = (s0 + 0 < n1) ? s0 + 0 : 0;
        int b = (s0 + 1 < n1) ? s0 + 1 : 0;
        int c = (s0 + 2 < n1) ? s0 + 2 : 0;
        int d = (s0 + 3 < n1) ? s0 + 3 : 0;
        wp10 = (const float4*)(w_sm + (size_t)a * Hc + kq1 * 256);
        wp11 = (const float4*)(w_sm + (size_t)b * Hc + kq1 * 256);
        wp12 = (const float4*)(w_sm + (size_t)c * Hc + kq1 * 256);
        wp13 = (const float4*)(w_sm + (size_t)d * Hc + kq1 * 256);
    }
    const float4* wp20; const float4* wp21; const float4* wp22; const float4* wp23;
    {
        int s0 = 4 * g2v;
        int a = (s0 + 0 < n2) ? s0 + 0 : 0;
        int b = (s0 + 1 < n2) ? s0 + 1 : 0;
        int c = (s0 + 2 < n2) ? s0 + 2 : 0;
        int d = (s0 + 3 < n2) ? s0 + 3 : 0;
        wp20 = (const float4*)(w_sm + (size_t)(n1 + a) * Hc + kq2 * 128);
        wp21 = (const float4*)(w_sm + (size_t)(n1 + b) * Hc + kq2 * 128);
        wp22 = (const float4*)(w_sm + (size_t)(n1 + c) * Hc + kq2 * 128);
        wp23 = (const float4*)(w_sm + (size_t)(n1 + d) * Hc + kq2 * 128);
    }

    float zv0 = 0.f, zv1 = 0.f, zv2 = 0.f, zv3 = 0.f;
    float ho0 = 0.f, ho1 = 0.f, ho2 = 0.f, ho3 = 0.f;

    for (int t = 0; t < Sc; t++) {
        const unsigned par = (unsigned)(t & 1);

        // prefetch x-projection inputs for this step's finalize (long-latency L2 loads)
        float px0 = 0.f, px1 = 0.f, px2 = 0.f, px3 = 0.f;
        if (warp < 4) {
#pragma unroll
            for (int c = 0; c < 4; c++) {
                int s = 4 * warp + c;
                if (s < n1) {
                    int cc = bid + s * NB;
                    bool isz = (s < n2);
                    int j = isz ? cc : cc - 1024;
                    float v = isz ? __ldcg(&g_xz[((size_t)t * Hc + j) * Bc + lane])
                                  : __ldcg(&g_xr[((size_t)t * Hc + j) * Bc + lane]);
                    if (c == 0) px0 = v; else if (c == 1) px1 = v;
                    else if (c == 2) px2 = v; else px3 = v;
                }
            }
        }
        float pg0 = 0.f, pg1 = 0.f, pg2 = 0.f, pg3 = 0.f;
        if (warp < 2) {
#pragma unroll
            for (int c = 0; c < 4; c++) {
                int s = 4 * warp + c;
                if (s < n2) {
                    int j = bid + s * NB;
                    float v = __ldcg(&g_xg[((size_t)t * Hc + j) * Bc + lane]);
                    if (c == 0) pg0 = v; else if (c == 1) pg1 = v;
                    else if (c == 2) pg2 = v; else pg3 = v;
                }
            }
        }

        // ---- phase 1: wait own h chunk, compute partials (4 cols x 256 k) ----
        mb_wait(mb0 + kq1 * 8, par);
        float a0 = 0.f, a1 = 0.f, a2 = 0.f, a3 = 0.f;
        {
            const float* hp = buf + kq1 * 256 * Bc + lane;
#pragma unroll 2
            for (int k4 = 0; k4 < 64; k4++) {
                float4 wa = wp10[k4]; float4 wb = wp11[k4];
                float4 wc = wp12[k4]; float4 wd = wp13[k4];
                float v0 = hp[0], v1 = hp[Bc], v2 = hp[2 * Bc], v3 = hp[3 * Bc];
                a0 += v0 * wa.x; a0 += v1 * wa.y; a0 += v2 * wa.z; a0 += v3 * wa.w;
                a1 += v0 * wb.x; a1 += v1 * wb.y; a1 += v2 * wb.z; a1 += v3 * wb.w;
                a2 += v0 * wc.x; a2 += v1 * wc.y; a2 += v2 * wc.z; a2 += v3 * wc.w;
                a3 += v0 * wd.x; a3 += v1 * wd.y; a3 += v2 * wd.z; a3 += v3 * wd.w;
                hp += 4 * Bc;
            }
        }
        if (kq1 > 0) {
            red_sm[(warp * 4 + 0) * 32 + lane] = a0;
            red_sm[(warp * 4 + 1) * 32 + lane] = a1;
            red_sm[(warp * 4 + 2) * 32 + lane] = a2;
            red_sm[(warp * 4 + 3) * 32 + lane] = a3;
        }
        __syncthreads();

        if (warp < 4) {
#pragma unroll
            for (int c = 0; c < 4; c++) {
                int s = 4 * warp + c;
                if (s < n1) {
                    int cc = bid + s * NB;
                    bool isz = (s < n2);
                    int j = isz ? cc : cc - 1024;
                    float acc = (c == 0) ? a0 : (c == 1) ? a1 : (c == 2) ? a2 : a3;
                    acc += red_sm[((warp + 4)  * 4 + c) * 32 + lane];
                    acc += red_sm[((warp + 8)  * 4 + c) * 32 + lane];
                    acc += red_sm[((warp + 12) * 4 + c) * 32 + lane];
                    float xin = (c == 0) ? px0 : (c == 1) ? px1 : (c == 2) ? px2 : px3;
                    float val = sigm(acc + xin);
                    float hv = buf[j * Bc + lane];
                    if (isz) {
                        if (c == 0) { zv0 = val; ho0 = hv; }
                        else if (c == 1) { zv1 = val; ho1 = hv; }
                        else if (c == 2) { zv2 = val; ho2 = hv; }
                        else { zv3 = val; ho3 = hv; }
                    } else {
                        __stcg(&g_rh[j * Bc + lane], val * hv);
                    }
                }
            }
        }
        ep++; grid_bar(bid, NB, ep);

        // kick off stage of r*h (overwrites buf; all P1 reads done at grid_bar)
        if (tid == 0) {
#pragma unroll
            for (int q = 0; q < 4; q++) {
                mb_expect(mbr0 + q * 8, 32768u);
                g2s(bufa + q * 32768u, g_rh + q * 8192, 32768u, mbr0 + q * 8);
            }
        }

        // ---- phase 2: wait own rh chunk, partials (4 cols x 128 k) ----
        mb_wait(mbr0 + (kq2 >> 1) * 8, par);
        float b0 = 0.f, b1 = 0.f, b2 = 0.f, b3 = 0.f;
        {
            const float* hp = buf + kq2 * 128 * Bc + lane;
#pragma unroll 2
            for (int k4 = 0; k4 < 32; k4++) {
                float4 wa = wp20[k4]; float4 wb = wp21[k4];
                float4 wc = wp22[k4]; float4 wd = wp23[k4];
                float v0 = hp[0], v1 = hp[Bc], v2 = hp[2 * Bc], v3 = hp[3 * Bc];
                b0 += v0 * wa.x; b0 += v1 * wa.y; b0 += v2 * wa.z; b0 += v3 * wa.w;
                b1 += v0 * wb.x; b1 += v1 * wb.y; b1 += v2 * wb.z; b1 += v3 * wb.w;
                b2 += v0 * wc.x; b2 += v1 * wc.y; b2 += v2 * wc.z; b2 += v3 * wc.w;
                b3 += v0 * wd.x; b3 += v1 * wd.y; b3 += v2 * wd.z; b3 += v3 * wd.w;
                hp += 4 * Bc;
            }
        }
        if (kq2 > 0) {
            red_sm[(warp * 4 + 0) * 32 + lane] = b0;
            red_sm[(warp * 4 + 1) * 32 + lane] = b1;
            red_sm[(warp * 4 + 2) * 32 + lane] = b2;
            red_sm[(warp * 4 + 3) * 32 + lane] = b3;
        }
        __syncthreads();

        if (warp < 2) {
#pragma unroll
            for (int c = 0; c < 4; c++) {
                int s = 4 * warp + c;
                if (s < n2) {
                    int j = bid + s * NB;
                    float acc = (c == 0) ? b0 : (c == 1) ? b1 : (c == 2) ? b2 : b3;
#pragma unroll
                    for (int p = 1; p < 8; p++)
                        acc += red_sm[((warp + 2 * p) * 4 + c) * 32 + lane];
                    float xin = (c == 0) ? pg0 : (c == 1) ? pg1 : (c == 2) ? pg2 : pg3;
                    float gg = fast_tanh(acc + xin);
                    float z  = (c == 0) ? zv0 : (c == 1) ? zv1 : (c == 2) ? zv2 : zv3;
                    float ho = (c == 0) ? ho0 : (c == 1) ? ho1 : (c == 2) ? ho2 : ho3;
                    float hn = z * ho + (1.0f - z) * gg;
                    __stcg(&g_h[j * Bc + lane], hn);
                    g_y[((size_t)t * Hc + j) * Bc + lane] = hn;
                }
            }
        }
        ep++; grid_bar(bid, NB, ep);

        // kick off stage of h(t) for step t+1 (overwrites buf; P2 reads done)
        if (tid == 0 && t + 1 < Sc) {
#pragma unroll
            for (int q = 0; q < 4; q++) {
                mb_expect(mb0 + q * 8, 32768u);
                g2s(bufa + q * 32768u, g_h + q * 8192, 32768u, mb0 + q * 8);
            }
        }
    }

    // write final hidden state for this layer: d_out[HID_OFF + b*2H + layer*H + j]
    for (int s = warp; s < n2; s += 16) {
        int j = bid + s * NB;
        dout[HID_OFF + (size_t)lane * (2 * Hc) + (size_t)layer * Hc + j] =
            __ldcg(&g_h[j * Bc + lane]);
    }
}

// ---------------- host ----------------
extern "C" void kernel_launch(void* const* d_in, const int* in_sizes, int n_in,
                              void* d_out, int out_size) {
    const float* x    = (const float*)d_in[0];
    const float* Wxz0 = (const float*)d_in[1];
    const float* bxz0 = (const float*)d_in[2];
    const float* Whz0 = (const float*)d_in[3];
    const float* Wxr0 = (const float*)d_in[4];
    const float* bxr0 = (const float*)d_in[5];
    const float* Whr0 = (const float*)d_in[6];
    const float* Wxg0 = (const float*)d_in[7];
    const float* bxg0 = (const float*)d_in[8];
    const float* Whg0 = (const float*)d_in[9];
    const float* Wxz1 = (const float*)d_in[10];
    const float* bxz1 = (const float*)d_in[11];
    const float* Whz1 = (const float*)d_in[12];
    const float* Wxr1 = (const float*)d_in[13];
    const float* bxr1 = (const float*)d_in[14];
    const float* Whr1 = (const float*)d_in[15];
    const float* Wxg1 = (const float*)d_in[16];
    const float* bxg1 = (const float*)d_in[17];
    const float* Whg1 = (const float*)d_in[18];
    const float* Wout = (const float*)d_in[19];
    const float* bout = (const float*)d_in[20];
    float* out = (float*)d_out;

    int dev = 0;
    cudaGetDevice(&dev);
    int sm = 148;
    cudaDeviceGetAttribute(&sm, cudaDevAttrMultiProcessorCount, dev);
    int NB = (sm < 148) ? sm : 148;
    int slots = (2048 + NB - 1) / NB + (1024 + NB - 1) / NB;
    size_t smemB = ((size_t)Hc * Bc + (size_t)slots * Hc + 16 * 4 * 32 + 16) * sizeof(float);
    cudaFuncSetAttribute(recur_kernel, cudaFuncAttributeMaxDynamicSharedMemorySize, (int)smemB);

    dim3 pg(Sc, Hc / 128, 3);

    // Layer 0
    proj_kernel<<<pg, 256>>>(x, Wxz0, bxz0, Wxr0, bxr0, Wxg0, bxg0, Ic, 0);
    recur_kernel<<<NB, THREADS, smemB>>>(Whz0, Whr0, Whg0, 0, out);
    // Layer 1 (input projections read g_y written by layer-0 recurrence)
    proj_kernel<<<pg, 256>>>(x, Wxz1, bxz1, Wxr1, bxr1, Wxg1, bxg1, Hc, 1);
    recur_kernel<<<NB, THREADS, smemB>>>(Whz1, Whr1, Whg1, 1, out);
    // Output projection
    dim3 og(Sc, Oc / 128, 1);
    outproj_kernel<<<og, 256>>>(Wout, bout, out);
}